// round 5
// baseline (speedup 1.0000x reference)
#include <cuda_runtime.h>
#include <math.h>

#define N_MAX 10000
#define E_MAX 160000
#define HD 64
#define NW 8
#define NWE 16
#define EB 8
#define RC_F 4.5f
#define PI_F 3.14159265358979323846f

typedef unsigned long long ull;

__device__ __forceinline__ ull fma2(ull a, ull b, ull c) {
    ull d; asm("fma.rn.f32x2 %0,%1,%2,%3;" : "=l"(d) : "l"(a), "l"(b), "l"(c)); return d;
}
__device__ __forceinline__ ull mul2(ull a, ull b) {
    ull d; asm("mul.rn.f32x2 %0,%1,%2;" : "=l"(d) : "l"(a), "l"(b)); return d;
}
__device__ __forceinline__ ull add2(ull a, ull b) {
    ull d; asm("add.rn.f32x2 %0,%1,%2;" : "=l"(d) : "l"(a), "l"(b)); return d;
}
__device__ __forceinline__ ull packdup(float x) {
    ull d; asm("mov.b64 %0,{%1,%1};" : "=l"(d) : "f"(x)); return d;
}
__device__ __forceinline__ float2 unpack2(ull a) {
    float2 v; asm("mov.b64 {%0,%1},%2;" : "=f"(v.x), "=f"(v.y) : "l"(a)); return v;
}
__device__ __forceinline__ void cpasync16(unsigned int dst, const void* src) {
    asm volatile("cp.async.cg.shared.global [%0], [%1], 16;" :: "r"(dst), "l"(src));
}
__device__ __forceinline__ void cp_commit() {
    asm volatile("cp.async.commit_group;" ::: "memory");
}
__device__ __forceinline__ void cp_wait1() {
    asm volatile("cp.async.wait_group 1;" ::: "memory");
}
__device__ __forceinline__ void cp_wait0() {
    asm volatile("cp.async.wait_group 0;" ::: "memory");
}

// ---- device scratch ----
__device__ int   g_cnt[N_MAX];
__device__ int   g_off[N_MAX + 1];
__device__ int   g_perm[E_MAX];
__device__ int   g_zj[E_MAX + 8];
__device__ int   g_ctr;
__device__ float g_ZS[256 * 64];
__device__ float g_ZD[256 * 64];
__device__ ull   g_attr[(size_t)(E_MAX + 8) * 64];   // duplicated pairs, sorted order
__device__ ull   g_meta[(size_t)(E_MAX + 8) * 10];   // duplicated geometry, sorted order
__device__ float g_accI[N_MAX * HD];
__device__ float g_accA[N_MAX * HD * 3];
__device__ float g_accS[N_MAX * HD * 6];

// ------------------------------------------------------------------
// Counting sort of edges by src
// ------------------------------------------------------------------
__global__ void k_zero(int n, int nE) {
    int i = blockIdx.x * blockDim.x + threadIdx.x;
    if (i == 0) g_ctr = 0;
    if (i < 8) g_zj[nE + i] = 0;
    if (i < n) g_cnt[i] = 0;
}

__global__ void k_count(const int* __restrict__ ei, int nE) {
    int e = blockIdx.x * blockDim.x + threadIdx.x;
    if (e < nE) atomicAdd(&g_cnt[ei[e]], 1);
}

__global__ void k_scan(int n) {
    __shared__ int wsum[32];
    int tid = threadIdx.x, lane = tid & 31, wid = tid >> 5;
    const int CH = 16;
    int beg = tid * CH;
    int loc[CH];
    int s = 0;
    if (beg + CH <= n) {
        int4 a0 = *(const int4*)&g_cnt[beg];
        int4 a1 = *(const int4*)&g_cnt[beg + 4];
        int4 a2 = *(const int4*)&g_cnt[beg + 8];
        int4 a3 = *(const int4*)&g_cnt[beg + 12];
        int v[CH] = {a0.x,a0.y,a0.z,a0.w, a1.x,a1.y,a1.z,a1.w,
                     a2.x,a2.y,a2.z,a2.w, a3.x,a3.y,a3.z,a3.w};
        #pragma unroll
        for (int i = 0; i < CH; i++) { loc[i] = s; s += v[i]; }
    } else {
        #pragma unroll
        for (int i = 0; i < CH; i++) {
            loc[i] = s;
            int idx = beg + i;
            if (idx < n) s += g_cnt[idx];
        }
    }
    int inc = s;
    #pragma unroll
    for (int o = 1; o < 32; o <<= 1) {
        int t = __shfl_up_sync(0xffffffffu, inc, o);
        if (lane >= o) inc += t;
    }
    if (lane == 31) wsum[wid] = inc;
    __syncthreads();
    if (wid == 0) {
        int v = wsum[lane];
        #pragma unroll
        for (int o = 1; o < 32; o <<= 1) {
            int t = __shfl_up_sync(0xffffffffu, v, o);
            if (lane >= o) v += t;
        }
        wsum[lane] = v;
    }
    __syncthreads();
    int excl = inc - s + (wid ? wsum[wid - 1] : 0);
    #pragma unroll
    for (int i = 0; i < CH; i++) {
        int idx = beg + i;
        if (idx < n) { g_off[idx] = excl + loc[i]; g_cnt[idx] = 0; }
    }
    if (tid == 1023) g_off[n] = wsum[31];
}

__global__ void k_scatter(const int* __restrict__ ei, int nE) {
    int e = blockIdx.x * blockDim.x + threadIdx.x;
    if (e < nE) {
        int s = ei[e];
        int pos = g_off[s] + atomicAdd(&g_cnt[s], 1);
        g_perm[pos] = e;
    }
}

// ------------------------------------------------------------------
// Precompute ZS/ZD tables over distinct z values
// ------------------------------------------------------------------
__global__ void k_pre(const float* __restrict__ emb, const float* __restrict__ e2w,
                      const float* __restrict__ e2b) {
    int zz = blockIdx.x;
    int h = threadIdx.x;
    __shared__ float er[64];
    er[h] = emb[zz * 64 + h];
    __syncthreads();
    float ss = e2b[h], sd = 0.f;
    #pragma unroll 8
    for (int j = 0; j < 64; j++) {
        ss = fmaf(e2w[h * 128 + j], er[j], ss);
        sd = fmaf(e2w[h * 128 + 64 + j], er[j], sd);
    }
    g_ZS[zz * 64 + h] = ss;
    g_ZD[zz * 64 + h] = sd;
}

// ------------------------------------------------------------------
// Gather edge data into sorted order: attr duplicated, meta, zj
// ------------------------------------------------------------------
__global__ void k_gather(const int* __restrict__ ei, const int* __restrict__ z,
                         const float* __restrict__ ew, const float* __restrict__ evn,
                         const float* __restrict__ attr, int nE)
{
    int t = blockIdx.x * blockDim.x + threadIdx.x;
    int s = t >> 3, sub = t & 7;
    if (s >= nE) return;
    int e = g_perm[s];
    const float2* src = (const float2*)(attr + (size_t)e * 64) + sub * 4;
    ull* dst = g_attr + (size_t)s * 64 + sub * 8;
    #pragma unroll
    for (int k = 0; k < 4; k++) {
        float2 v = src[k];
        dst[2 * k]     = packdup(v.x);
        dst[2 * k + 1] = packdup(v.y);
    }
    if (sub == 0) {
        g_zj[s] = z[ei[nE + e]];
        float w = ew[e];
        float C = (w < RC_F) ? 0.5f * (cosf(w * (PI_F / RC_F)) + 1.0f) : 0.0f;
        float vx = evn[3 * e + 0], vy = evn[3 * e + 1], vz = evn[3 * e + 2];
        float tr3 = (vx * vx + vy * vy + vz * vz) * (1.0f / 3.0f);
        ull* mp = g_meta + (size_t)s * 10;
        mp[0] = packdup(C);
        mp[1] = packdup(vx); mp[2] = packdup(vy); mp[3] = packdup(vz);
        mp[4] = packdup(vx * vx - tr3);
        mp[5] = packdup(vy * vy - tr3);
        mp[6] = packdup(vz * vz - tr3);
        mp[7] = packdup(vx * vy); mp[8] = packdup(vx * vz); mp[9] = packdup(vy * vz);
    }
}

// ------------------------------------------------------------------
// Edge kernel: warp/atom, streaming cp.async double-buffered batches.
// ------------------------------------------------------------------
struct Acc { ull I, Ax, Ay, Az, Sxx, Syy, Szz, Sxy, Sxz, Syz; };

__device__ __forceinline__ void issue_copy(int idx, unsigned int attDst,
                                           unsigned int metDst, int lane)
{
    const char* asrc = (const char*)(g_attr + (size_t)idx * 64) + lane * 16;
    #pragma unroll
    for (int k = 0; k < 8; k++)
        cpasync16(attDst + lane * 16 + k * 512, asrc + (size_t)k * 512);
    const char* msrc = (const char*)(g_meta + (size_t)idx * 10);
    cpasync16(metDst + lane * 16, msrc + lane * 16);
    if (lane < 8)
        cpasync16(metDst + 512 + lane * 16, msrc + 512 + lane * 16);
}

__global__ __launch_bounds__(NWE * 32, 1)
void k_edge(const int* __restrict__ z,
            const float* __restrict__ d1w, const float* __restrict__ d1b,
            const float* __restrict__ d2w, const float* __restrict__ d2b,
            const float* __restrict__ d3w, const float* __restrict__ d3b,
            int n)
{
    extern __shared__ float sm[];
    float* t1f = sm;                       // 4096
    float* t2f = t1f + 4096;
    float* t3f = t2f + 4096;
    float* bbf = t3f + 4096;               // 192
    float* attf = bbf + 192;               // NWE * 2048 (two 4KB buffers per warp)
    float* metf = attf + NWE * 2048;       // NWE * 320 (two 640B buffers per warp)

    int tid = threadIdx.x;
    for (int i = tid; i < 1024; i += blockDim.x) {
        int j2 = i >> 5, l = i & 31;
        int j0 = 2 * j2, j1 = j0 + 1, h0 = 2 * l, h1 = h0 + 1;
        int base = i * 4;
        t1f[base + 0] = d1w[h0 * 64 + j0]; t1f[base + 1] = d1w[h1 * 64 + j0];
        t1f[base + 2] = d1w[h0 * 64 + j1]; t1f[base + 3] = d1w[h1 * 64 + j1];
        t2f[base + 0] = d2w[h0 * 64 + j0]; t2f[base + 1] = d2w[h1 * 64 + j0];
        t2f[base + 2] = d2w[h0 * 64 + j1]; t2f[base + 3] = d2w[h1 * 64 + j1];
        t3f[base + 0] = d3w[h0 * 64 + j0]; t3f[base + 1] = d3w[h1 * 64 + j0];
        t3f[base + 2] = d3w[h0 * 64 + j1]; t3f[base + 3] = d3w[h1 * 64 + j1];
    }
    for (int i = tid; i < 64; i += blockDim.x) {
        bbf[i] = d1b[i]; bbf[64 + i] = d2b[i]; bbf[128 + i] = d3b[i];
    }
    __syncthreads();

    int warp = tid >> 5, lane = tid & 31;
    const ulonglong2* t1q = (const ulonglong2*)t1f;
    const ulonglong2* t2q = (const ulonglong2*)t2f;
    const ulonglong2* t3q = (const ulonglong2*)t3f;

    float* attw = attf + warp * 2048;
    float* metw = metf + warp * 320;
    unsigned int attA = (unsigned int)__cvta_generic_to_shared(attw);
    unsigned int metA = (unsigned int)__cvta_generic_to_shared(metw);

    ull bias1 = ((const ull*)bbf)[lane];
    ull bias2 = ((const ull*)(bbf + 64))[lane];
    ull bias3 = ((const ull*)(bbf + 128))[lane];

    for (;;) {
        int atom;
        if (lane == 0) atom = atomicAdd(&g_ctr, 1);
        atom = __shfl_sync(0xffffffffu, atom, 0);
        if (atom >= n) break;

        int e0 = g_off[atom], e1 = g_off[atom + 1];
        Acc A = {0ull,0ull,0ull,0ull,0ull,0ull,0ull,0ull,0ull,0ull};

        if (e0 < e1) {
            ull zS2 = ((const ull*)g_ZS)[z[atom] * 32 + lane];
            issue_copy(e0, attA, metA, lane);
            cp_commit();
            int buf = 0;

            for (int idx = e0; idx < e1; idx += EB) {
                bool more = (idx + EB) < e1;
                if (more) {
                    issue_copy(idx + EB, attA + (buf ^ 1) * 4096,
                               metA + (buf ^ 1) * 640, lane);
                    cp_commit();
                    cp_wait1();
                } else {
                    cp_wait0();
                }
                __syncwarp();

                int zjp[EB];
                #pragma unroll
                for (int b = 0; b < EB; b++) zjp[b] = g_zj[idx + b];

                ull s1[EB], s2[EB], s3[EB];
                #pragma unroll
                for (int b = 0; b < EB; b++) { s1[b] = bias1; s2[b] = bias2; s3[b] = bias3; }

                const ulonglong2* attq = (const ulonglong2*)(attw + buf * 1024);
                #pragma unroll 4
                for (int j2 = 0; j2 < 32; j2++) {
                    ulonglong2 q1 = t1q[j2 * 32 + lane];
                    ulonglong2 q2 = t2q[j2 * 32 + lane];
                    ulonglong2 q3 = t3q[j2 * 32 + lane];
                    #pragma unroll
                    for (int b = 0; b < EB; b++) {
                        ulonglong2 aa = attq[b * 32 + j2];
                        s1[b] = fma2(q1.x, aa.x, s1[b]);
                        s2[b] = fma2(q2.x, aa.x, s2[b]);
                        s3[b] = fma2(q3.x, aa.x, s3[b]);
                        s1[b] = fma2(q1.y, aa.y, s1[b]);
                        s2[b] = fma2(q2.y, aa.y, s2[b]);
                        s3[b] = fma2(q3.y, aa.y, s3[b]);
                    }
                }

                int nb = e1 - idx; if (nb > EB) nb = EB;
                const ull* metu = (const ull*)(metw + buf * 160);
                #pragma unroll
                for (int b = 0; b < EB; b++) {
                    if (b >= nb) break;
                    ull zd = ((const ull*)g_ZD)[zjp[b] * 32 + lane];
                    const ull* mp = metu + b * 10;
                    ull zfac = mul2(mp[0], add2(zS2, zd));
                    ull g1 = mul2(s1[b], zfac);
                    ull g2 = mul2(s2[b], zfac);
                    ull g3 = mul2(s3[b], zfac);
                    A.I   = add2(A.I, g1);
                    A.Ax  = fma2(g2, mp[1], A.Ax);
                    A.Ay  = fma2(g2, mp[2], A.Ay);
                    A.Az  = fma2(g2, mp[3], A.Az);
                    A.Sxx = fma2(g3, mp[4], A.Sxx);
                    A.Syy = fma2(g3, mp[5], A.Syy);
                    A.Szz = fma2(g3, mp[6], A.Szz);
                    A.Sxy = fma2(g3, mp[7], A.Sxy);
                    A.Sxz = fma2(g3, mp[8], A.Sxz);
                    A.Syz = fma2(g3, mp[9], A.Syz);
                }
                buf ^= 1;
                __syncwarp();
            }
        }

        int base = atom * 64 + lane * 2;
        float2 vI = unpack2(A.I);
        g_accI[base] = vI.x; g_accI[base + 1] = vI.y;
        float2 vAx = unpack2(A.Ax), vAy = unpack2(A.Ay), vAz = unpack2(A.Az);
        int bA = base * 3;
        g_accA[bA + 0] = vAx.x; g_accA[bA + 1] = vAy.x; g_accA[bA + 2] = vAz.x;
        g_accA[bA + 3] = vAx.y; g_accA[bA + 4] = vAy.y; g_accA[bA + 5] = vAz.y;
        float2 vSxx = unpack2(A.Sxx), vSyy = unpack2(A.Syy), vSzz = unpack2(A.Szz);
        float2 vSxy = unpack2(A.Sxy), vSxz = unpack2(A.Sxz), vSyz = unpack2(A.Syz);
        int bS = base * 6;
        g_accS[bS + 0] = vSxx.x; g_accS[bS + 1] = vSyy.x; g_accS[bS + 2] = vSzz.x;
        g_accS[bS + 3] = vSxy.x; g_accS[bS + 4] = vSxz.x; g_accS[bS + 5] = vSyz.x;
        g_accS[bS + 6] = vSxx.y; g_accS[bS + 7] = vSyy.y; g_accS[bS + 8] = vSzz.y;
        g_accS[bS + 9] = vSxy.y; g_accS[bS + 10] = vSxz.y; g_accS[bS + 11] = vSyz.y;
    }
}

// ------------------------------------------------------------------
// Post: tn -> LN -> MLP -> n0 -> diagonal output (merged)
// ------------------------------------------------------------------
__device__ __forceinline__ float sq(float x) { return x * x; }
__device__ __forceinline__ float silu(float x) { return x / (1.0f + expf(-x)); }

__global__ void k_post(const float* __restrict__ lng, const float* __restrict__ lnb,
                       const float* __restrict__ w1, const float* __restrict__ b1,
                       const float* __restrict__ w2, const float* __restrict__ b2,
                       const float* __restrict__ m0, const float* __restrict__ m1,
                       const float* __restrict__ m2, float* __restrict__ out, int n)
{
    extern __shared__ float sm[];
    float* w1T  = sm;               // [j(64)][o(128)]
    float* w2nT = w1T + 64 * 128;   // [j(128)][h(64)]
    float* m0T  = w2nT + 128 * 64;  // [h][k]
    float* msT  = m0T + 64 * 64;    // [h][k] of m1+m2
    float* sb1  = msT + 64 * 64;    // 128
    float* sb2  = sb1 + 128;        // 64
    float* slg  = sb2 + 64;
    float* slb  = slg + 64;
    float* wk   = slb + 64;         // NW * 320

    int tid = threadIdx.x;
    for (int i = tid; i < 64 * 128; i += blockDim.x) {
        int j = i >> 7, o = i & 127;
        w1T[i] = w1[o * 64 + j];
    }
    for (int i = tid; i < 128 * 64; i += blockDim.x) {
        int j = i >> 6, h = i & 63;
        w2nT[i] = w2[h * 3 * 128 + j];
    }
    for (int i = tid; i < 64 * 64; i += blockDim.x) {
        int h = i >> 6, k = i & 63;
        m0T[i] = m0[k * 64 + h];
        msT[i] = m1[k * 64 + h] + m2[k * 64 + h];
    }
    for (int i = tid; i < 128; i += blockDim.x) sb1[i] = b1[i];
    for (int i = tid; i < 64; i += blockDim.x) {
        sb2[i] = b2[3 * i]; slg[i] = lng[i]; slb[i] = lnb[i];
    }
    __syncthreads();

    int warp = tid >> 5, lane = tid & 31;
    float* nm  = wk + warp * 320;   // 64
    float* h1  = nm + 64;           // 128
    float* wkv = h1 + 128;          // 128
    const float2* w2n2 = (const float2*)w2nT;
    const float2* m0v  = (const float2*)m0T;
    const float2* msv  = (const float2*)msT;

    for (int atom = blockIdx.x * NW + warp; atom < n; atom += gridDim.x * NW) {
        int h0 = lane * 2;
        int base = atom * 64 + h0;
        float i0a = g_accI[base], i0b = g_accI[base + 1];
        const float* Ap = g_accA + base * 3;
        const float* Sp = g_accS + base * 6;
        float tna = sq(i0a + Sp[0]) + sq(i0a + Sp[1]) + sq(i0a + Sp[2])
                  + 2.0f * (sq(Sp[3]) + sq(Sp[4]) + sq(Sp[5]) + sq(Ap[0]) + sq(Ap[1]) + sq(Ap[2]));
        float tnb = sq(i0b + Sp[6]) + sq(i0b + Sp[7]) + sq(i0b + Sp[8])
                  + 2.0f * (sq(Sp[9]) + sq(Sp[10]) + sq(Sp[11]) + sq(Ap[3]) + sq(Ap[4]) + sq(Ap[5]));
        wkv[h0] = i0a; wkv[h0 + 1] = i0b;

        float s = tna + tnb;
        for (int o = 16; o; o >>= 1) s += __shfl_xor_sync(0xffffffffu, s, o);
        float mu = s * (1.0f / 64.0f);
        float da = tna - mu, db = tnb - mu;
        float vs = da * da + db * db;
        for (int o = 16; o; o >>= 1) vs += __shfl_xor_sync(0xffffffffu, vs, o);
        float inv = rsqrtf(vs * (1.0f / 64.0f) + 1e-5f);
        nm[h0]     = da * inv * slg[h0] + slb[h0];
        nm[h0 + 1] = db * inv * slg[h0 + 1] + slb[h0 + 1];
        __syncwarp();

        #pragma unroll
        for (int p = 0; p < 4; p++) {
            int o = lane + 32 * p;
            float acc = sb1[o];
            #pragma unroll 8
            for (int j = 0; j < 64; j++) acc = fmaf(w1T[j * 128 + o], nm[j], acc);
            h1[o] = silu(acc);
        }
        __syncwarp();

        float2 acc2 = ((const float2*)sb2)[lane];
        #pragma unroll 8
        for (int j = 0; j < 128; j++) {
            float hv = h1[j];
            float2 wv = w2n2[j * 32 + lane];
            acc2.x = fmaf(wv.x, hv, acc2.x);
            acc2.y = fmaf(wv.y, hv, acc2.y);
        }
        float n0x = silu(acc2.x), n0y = silu(acc2.y);

        float2 d1 = {0.f, 0.f};
        #pragma unroll 8
        for (int h = 0; h < 64; h++) {
            float a = wkv[h];
            float2 m = m0v[h * 32 + lane];
            d1.x = fmaf(m.x, a, d1.x);
            d1.y = fmaf(m.y, a, d1.y);
        }
        d1.x *= n0x; d1.y *= n0y;
        __syncwarp();
        wkv[h0] = d1.x; wkv[h0 + 1] = d1.y;
        __syncwarp();

        float2 tt = {0.f, 0.f};
        #pragma unroll 8
        for (int h = 0; h < 64; h++) {
            float d = wkv[h];
            float2 m = msv[h * 32 + lane];
            tt.x = fmaf(m.x, d, tt.x);
            tt.y = fmaf(m.y, d, tt.y);
        }
        float vx = d1.x + n0x * tt.x;
        float vy = d1.y + n0y * tt.y;

        float2* o = (float2*)(out + (size_t)(atom * 64 + h0) * 9);
        o[0] = make_float2(vx, 0.f);
        o[1] = make_float2(0.f, 0.f);
        o[2] = make_float2(vx, 0.f);
        o[3] = make_float2(0.f, 0.f);
        o[4] = make_float2(vx, vy);
        o[5] = make_float2(0.f, 0.f);
        o[6] = make_float2(0.f, vy);
        o[7] = make_float2(0.f, 0.f);
        o[8] = make_float2(0.f, vy);
        __syncwarp();
    }
}

// ------------------------------------------------------------------
extern "C" void kernel_launch(void* const* d_in, const int* in_sizes, int n_in,
                              void* d_out, int out_size)
{
    const int*   z    = (const int*)d_in[0];
    const int*   ei   = (const int*)d_in[1];
    const float* ew   = (const float*)d_in[2];
    const float* evn  = (const float*)d_in[3];
    const float* attr = (const float*)d_in[4];
    const float* emb  = (const float*)d_in[5];
    const float* e2w  = (const float*)d_in[6];
    const float* e2b  = (const float*)d_in[7];
    const float* d1w  = (const float*)d_in[8];
    const float* d1b  = (const float*)d_in[9];
    const float* d2w  = (const float*)d_in[10];
    const float* d2b  = (const float*)d_in[11];
    const float* d3w  = (const float*)d_in[12];
    const float* d3b  = (const float*)d_in[13];
    const float* lng  = (const float*)d_in[14];
    const float* lnb  = (const float*)d_in[15];
    const float* w1   = (const float*)d_in[16];
    const float* b1   = (const float*)d_in[17];
    const float* w2   = (const float*)d_in[18];
    const float* b2   = (const float*)d_in[19];
    const float* m0   = (const float*)d_in[20];
    const float* m1   = (const float*)d_in[21];
    const float* m2   = (const float*)d_in[22];
    float* out = (float*)d_out;

    int n    = in_sizes[0];
    int nE   = in_sizes[2];
    int maxz = in_sizes[5] / 64;
    if (maxz > 256) maxz = 256;

    size_t smemE = (size_t)(3 * 4096 + 192 + NWE * 2048 + NWE * 320) * sizeof(float);
    size_t smemP = (size_t)(64 * 128 + 128 * 64 + 2 * 64 * 64 + 128 + 3 * 64 + NW * 320) * sizeof(float);
    cudaFuncSetAttribute(k_edge, cudaFuncAttributeMaxDynamicSharedMemorySize, (int)smemE);
    cudaFuncSetAttribute(k_post, cudaFuncAttributeMaxDynamicSharedMemorySize, (int)smemP);

    k_zero<<<(n + 255) / 256, 256>>>(n, nE);
    k_count<<<(nE + 255) / 256, 256>>>(ei, nE);
    k_pre<<<maxz, 64>>>(emb, e2w, e2b);
    k_scan<<<1, 1024>>>(n);
    k_scatter<<<(nE + 255) / 256, 256>>>(ei, nE);
    k_gather<<<(nE * 8 + 255) / 256, 256>>>(ei, z, ew, evn, attr, nE);

    k_edge<<<152, NWE * 32, smemE>>>(z, d1w, d1b, d2w, d2b, d3w, d3b, n);
    k_post<<<304, NW * 32, smemP>>>(lng, lnb, w1, b1, w2, b2, m0, m1, m2, out, n);
}

// round 6
// speedup vs baseline: 1.0912x; 1.0912x over previous
#include <cuda_runtime.h>
#include <math.h>

#define N_MAX 10000
#define E_MAX 160000
#define HD 64
#define NW 8
#define RC_F 4.5f
#define PI_F 3.14159265358979323846f

typedef unsigned long long ull;

__device__ __forceinline__ ull fma2(ull a, ull b, ull c) {
    ull d; asm("fma.rn.f32x2 %0,%1,%2,%3;" : "=l"(d) : "l"(a), "l"(b), "l"(c)); return d;
}
__device__ __forceinline__ ull mul2(ull a, ull b) {
    ull d; asm("mul.rn.f32x2 %0,%1,%2;" : "=l"(d) : "l"(a), "l"(b)); return d;
}
__device__ __forceinline__ ull add2(ull a, ull b) {
    ull d; asm("add.rn.f32x2 %0,%1,%2;" : "=l"(d) : "l"(a), "l"(b)); return d;
}
__device__ __forceinline__ ull packdup(float x) {
    ull d; asm("mov.b64 %0,{%1,%1};" : "=l"(d) : "f"(x)); return d;
}
__device__ __forceinline__ float2 unpack2(ull a) {
    float2 v; asm("mov.b64 {%0,%1},%2;" : "=f"(v.x), "=f"(v.y) : "l"(a)); return v;
}
__device__ __forceinline__ unsigned tf32r(float x) {
    unsigned u; asm("cvt.rna.tf32.f32 %0,%1;" : "=r"(u) : "f"(x)); return u;
}
__device__ __forceinline__ void mma8(float* c, unsigned a0, unsigned a1, unsigned a2,
                                     unsigned a3, unsigned b0, unsigned b1) {
    asm("mma.sync.aligned.m16n8k8.row.col.f32.tf32.tf32.f32 "
        "{%0,%1,%2,%3},{%4,%5,%6,%7},{%8,%9},{%0,%1,%2,%3};"
        : "+f"(c[0]), "+f"(c[1]), "+f"(c[2]), "+f"(c[3])
        : "r"(a0), "r"(a1), "r"(a2), "r"(a3), "r"(b0), "r"(b1));
}

// ---- device scratch ----
__device__ int   g_cnt[N_MAX];
__device__ int   g_off[N_MAX + 1];
__device__ int   g_perm[E_MAX];
__device__ int   g_zj[E_MAX];
__device__ int   g_ctr;
__device__ float g_ZS[256 * 64];
__device__ float g_ZD[256 * 64];
__device__ float g_meta[(size_t)E_MAX * 12];
__device__ uint2 g_WfHi[24 * 8 * 32];
__device__ uint2 g_WfLo[24 * 8 * 32];
__device__ float g_S[(size_t)(E_MAX + 128) * 192];
__device__ float g_accI[N_MAX * HD];
__device__ float g_accA[N_MAX * HD * 3];
__device__ float g_accS[N_MAX * HD * 6];

// ------------------------------------------------------------------
// Counting sort of edges by src
// ------------------------------------------------------------------
__global__ void k_zero(int n) {
    int i = blockIdx.x * blockDim.x + threadIdx.x;
    if (i == 0) g_ctr = 0;
    if (i < n) g_cnt[i] = 0;
}

__global__ void k_count(const int* __restrict__ ei, int nE) {
    int e = blockIdx.x * blockDim.x + threadIdx.x;
    if (e < nE) atomicAdd(&g_cnt[ei[e]], 1);
}

__global__ void k_scan(int n) {
    __shared__ int wsum[32];
    int tid = threadIdx.x, lane = tid & 31, wid = tid >> 5;
    const int CH = 16;
    int beg = tid * CH;
    int loc[CH];
    int s = 0;
    if (beg + CH <= n) {
        int4 a0 = *(const int4*)&g_cnt[beg];
        int4 a1 = *(const int4*)&g_cnt[beg + 4];
        int4 a2 = *(const int4*)&g_cnt[beg + 8];
        int4 a3 = *(const int4*)&g_cnt[beg + 12];
        int v[CH] = {a0.x,a0.y,a0.z,a0.w, a1.x,a1.y,a1.z,a1.w,
                     a2.x,a2.y,a2.z,a2.w, a3.x,a3.y,a3.z,a3.w};
        #pragma unroll
        for (int i = 0; i < CH; i++) { loc[i] = s; s += v[i]; }
    } else {
        #pragma unroll
        for (int i = 0; i < CH; i++) {
            loc[i] = s;
            int idx = beg + i;
            if (idx < n) s += g_cnt[idx];
        }
    }
    int inc = s;
    #pragma unroll
    for (int o = 1; o < 32; o <<= 1) {
        int t = __shfl_up_sync(0xffffffffu, inc, o);
        if (lane >= o) inc += t;
    }
    if (lane == 31) wsum[wid] = inc;
    __syncthreads();
    if (wid == 0) {
        int v = wsum[lane];
        #pragma unroll
        for (int o = 1; o < 32; o <<= 1) {
            int t = __shfl_up_sync(0xffffffffu, v, o);
            if (lane >= o) v += t;
        }
        wsum[lane] = v;
    }
    __syncthreads();
    int excl = inc - s + (wid ? wsum[wid - 1] : 0);
    #pragma unroll
    for (int i = 0; i < CH; i++) {
        int idx = beg + i;
        if (idx < n) { g_off[idx] = excl + loc[i]; g_cnt[idx] = 0; }
    }
    if (tid == 1023) g_off[n] = wsum[31];
}

__global__ void k_scatter(const int* __restrict__ ei, int nE) {
    int e = blockIdx.x * blockDim.x + threadIdx.x;
    if (e < nE) {
        int s = ei[e];
        int pos = g_off[s] + atomicAdd(&g_cnt[s], 1);
        g_perm[pos] = e;
    }
}

// ------------------------------------------------------------------
// ZS/ZD tables over distinct z values
// ------------------------------------------------------------------
__global__ void k_pre(const float* __restrict__ emb, const float* __restrict__ e2w,
                      const float* __restrict__ e2b) {
    int zz = blockIdx.x;
    int h = threadIdx.x;
    __shared__ float er[64];
    er[h] = emb[zz * 64 + h];
    __syncthreads();
    float ss = e2b[h], sd = 0.f;
    #pragma unroll 8
    for (int j = 0; j < 64; j++) {
        ss = fmaf(e2w[h * 128 + j], er[j], ss);
        sd = fmaf(e2w[h * 128 + 64 + j], er[j], sd);
    }
    g_ZS[zz * 64 + h] = ss;
    g_ZD[zz * 64 + h] = sd;
}

// ------------------------------------------------------------------
// Pack W (3 x [64h,64j]) into mma B-fragment layout, hi/lo tf32 split
// ------------------------------------------------------------------
__global__ void k_wprep(const float* __restrict__ d1w, const float* __restrict__ d2w,
                        const float* __restrict__ d3w) {
    int i = blockIdx.x * blockDim.x + threadIdx.x;
    if (i >= 24 * 8 * 32) return;
    int lane = i & 31, ks = (i >> 5) & 7, ntg = i >> 8;
    int m = ntg * 8 + (lane >> 2);          // output index 0..191
    int j0 = ks * 8 + (lane & 3);
    const float* W = (m < 64) ? d1w : (m < 128) ? d2w : d3w;
    int h = m & 63;
    float w0 = W[h * 64 + j0];
    float w1 = W[h * 64 + j0 + 4];
    unsigned h0 = tf32r(w0), h1 = tf32r(w1);
    unsigned l0 = tf32r(w0 - __uint_as_float(h0));
    unsigned l1 = tf32r(w1 - __uint_as_float(h1));
    g_WfHi[i] = make_uint2(h0, h1);
    g_WfLo[i] = make_uint2(l0, l1);
}

// ------------------------------------------------------------------
// Per-edge meta (geometry/cutoff) + zj, in sorted order
// ------------------------------------------------------------------
__global__ void k_gather(const int* __restrict__ ei, const int* __restrict__ z,
                         const float* __restrict__ ew, const float* __restrict__ evn,
                         int nE)
{
    int s = blockIdx.x * blockDim.x + threadIdx.x;
    if (s >= nE) return;
    int e = g_perm[s];
    g_zj[s] = z[ei[nE + e]];
    float w = ew[e];
    float C = (w < RC_F) ? 0.5f * (cosf(w * (PI_F / RC_F)) + 1.0f) : 0.0f;
    float vx = evn[3 * e + 0], vy = evn[3 * e + 1], vz = evn[3 * e + 2];
    float tr3 = (vx * vx + vy * vy + vz * vz) * (1.0f / 3.0f);
    float4* mp = (float4*)(g_meta + (size_t)s * 12);
    mp[0] = make_float4(C, vx, vy, vz);
    mp[1] = make_float4(vx * vx - tr3, vy * vy - tr3, vz * vz - tr3, vx * vy);
    mp[2] = make_float4(vx * vz, vy * vz, 0.f, 0.f);
}

// ------------------------------------------------------------------
// Tensor-core GEMM: S[s,192] = attr[perm[s],:64] @ Wt^T, tf32 hi/lo
// Block: 128 edges; 8 warps each own 16 edges, 2 passes of 12 n-tiles
// ------------------------------------------------------------------
__global__ __launch_bounds__(256, 1)
void k_gemm(const float* __restrict__ attr, int nE)
{
    extern __shared__ unsigned smu[];
    unsigned* aHi = smu;                 // 128 * 68
    unsigned* aLo = smu + 128 * 68;

    int tid = threadIdx.x;
    int sBase = blockIdx.x * 128;

    // load + hi/lo convert the 128x64 attr tile (2 threads per row)
    {
        int r = tid >> 1, half = tid & 1;
        int srow = sBase + r; if (srow >= nE) srow = nE - 1;
        int e = g_perm[srow];
        const float4* src = (const float4*)(attr + (size_t)e * 64 + half * 32);
        unsigned* dh = aHi + r * 68 + half * 32;
        unsigned* dl = aLo + r * 68 + half * 32;
        #pragma unroll
        for (int k = 0; k < 8; k++) {
            float4 v = src[k];
            unsigned h0 = tf32r(v.x), h1 = tf32r(v.y), h2 = tf32r(v.z), h3 = tf32r(v.w);
            dh[4 * k + 0] = h0; dh[4 * k + 1] = h1; dh[4 * k + 2] = h2; dh[4 * k + 3] = h3;
            dl[4 * k + 0] = tf32r(v.x - __uint_as_float(h0));
            dl[4 * k + 1] = tf32r(v.y - __uint_as_float(h1));
            dl[4 * k + 2] = tf32r(v.z - __uint_as_float(h2));
            dl[4 * k + 3] = tf32r(v.w - __uint_as_float(h3));
        }
    }
    __syncthreads();

    int warp = tid >> 5, lane = tid & 31;
    int g = lane >> 2, cc = lane & 3;
    int rowA = warp * 16 + g;

    #pragma unroll
    for (int p = 0; p < 2; p++) {
        float c[12][4];
        #pragma unroll
        for (int nt = 0; nt < 12; nt++) {
            c[nt][0] = 0.f; c[nt][1] = 0.f; c[nt][2] = 0.f; c[nt][3] = 0.f;
        }
        #pragma unroll
        for (int ks = 0; ks < 8; ks++) {
            int col = ks * 8 + cc;
            unsigned ah0 = aHi[rowA * 68 + col];
            unsigned ah1 = aHi[(rowA + 8) * 68 + col];
            unsigned ah2 = aHi[rowA * 68 + col + 4];
            unsigned ah3 = aHi[(rowA + 8) * 68 + col + 4];
            unsigned al0 = aLo[rowA * 68 + col];
            unsigned al1 = aLo[(rowA + 8) * 68 + col];
            unsigned al2 = aLo[rowA * 68 + col + 4];
            unsigned al3 = aLo[(rowA + 8) * 68 + col + 4];
            #pragma unroll
            for (int nt = 0; nt < 12; nt++) {
                int ntg = p * 12 + nt;
                uint2 bh = g_WfHi[(ntg * 8 + ks) * 32 + lane];
                uint2 bl = g_WfLo[(ntg * 8 + ks) * 32 + lane];
                mma8(c[nt], ah0, ah1, ah2, ah3, bh.x, bh.y);
                mma8(c[nt], ah0, ah1, ah2, ah3, bl.x, bl.y);
                mma8(c[nt], al0, al1, al2, al3, bh.x, bh.y);
            }
        }
        size_t eRow = (size_t)sBase + warp * 16 + g;
        #pragma unroll
        for (int nt = 0; nt < 12; nt++) {
            int m = (p * 12 + nt) * 8 + 2 * cc;
            *(float2*)&g_S[eRow * 192 + m]       = make_float2(c[nt][0], c[nt][1]);
            *(float2*)&g_S[(eRow + 8) * 192 + m] = make_float2(c[nt][2], c[nt][3]);
        }
    }
}

// ------------------------------------------------------------------
// Reduce: per atom, combine S rows with CZ + geometry into moments
// ------------------------------------------------------------------
struct Acc { ull I, Ax, Ay, Az, Sxx, Syy, Szz, Sxy, Sxz, Syz; };

__global__ __launch_bounds__(512, 1)
void k_reduce(const int* __restrict__ z,
              const float* __restrict__ d1b, const float* __restrict__ d2b,
              const float* __restrict__ d3b, int n)
{
    int lane = threadIdx.x & 31;
    ull bias1 = ((const ull*)d1b)[lane];
    ull bias2 = ((const ull*)d2b)[lane];
    ull bias3 = ((const ull*)d3b)[lane];

    for (;;) {
        int atom;
        if (lane == 0) atom = atomicAdd(&g_ctr, 1);
        atom = __shfl_sync(0xffffffffu, atom, 0);
        if (atom >= n) break;

        int e0 = g_off[atom], e1 = g_off[atom + 1];
        Acc A = {0ull,0ull,0ull,0ull,0ull,0ull,0ull,0ull,0ull,0ull};

        if (e0 < e1) {
            ull zS2 = ((const ull*)g_ZS)[z[atom] * 32 + lane];
            #pragma unroll 2
            for (int s = e0; s < e1; s++) {
                const ull* sp = (const ull*)(g_S + (size_t)s * 192);
                ull s1 = __ldg(sp + lane);
                ull s2 = __ldg(sp + 32 + lane);
                ull s3 = __ldg(sp + 64 + lane);
                int zj = __ldg(g_zj + s);
                ull zd = __ldg(((const ull*)g_ZD) + zj * 32 + lane);
                const float* mp = g_meta + (size_t)s * 12;
                float C   = __ldg(mp + 0);
                float vx  = __ldg(mp + 1), vy = __ldg(mp + 2), vz = __ldg(mp + 3);
                float sxx = __ldg(mp + 4), syy = __ldg(mp + 5), szz = __ldg(mp + 6);
                float sxy = __ldg(mp + 7), sxz = __ldg(mp + 8), syz = __ldg(mp + 9);

                ull zfac = mul2(packdup(C), add2(zS2, zd));
                ull g1 = mul2(add2(s1, bias1), zfac);
                ull g2 = mul2(add2(s2, bias2), zfac);
                ull g3 = mul2(add2(s3, bias3), zfac);
                A.I   = add2(A.I, g1);
                A.Ax  = fma2(g2, packdup(vx), A.Ax);
                A.Ay  = fma2(g2, packdup(vy), A.Ay);
                A.Az  = fma2(g2, packdup(vz), A.Az);
                A.Sxx = fma2(g3, packdup(sxx), A.Sxx);
                A.Syy = fma2(g3, packdup(syy), A.Syy);
                A.Szz = fma2(g3, packdup(szz), A.Szz);
                A.Sxy = fma2(g3, packdup(sxy), A.Sxy);
                A.Sxz = fma2(g3, packdup(sxz), A.Sxz);
                A.Syz = fma2(g3, packdup(syz), A.Syz);
            }
        }

        int base = atom * 64 + lane * 2;
        float2 vI = unpack2(A.I);
        g_accI[base] = vI.x; g_accI[base + 1] = vI.y;
        float2 vAx = unpack2(A.Ax), vAy = unpack2(A.Ay), vAz = unpack2(A.Az);
        int bA = base * 3;
        g_accA[bA + 0] = vAx.x; g_accA[bA + 1] = vAy.x; g_accA[bA + 2] = vAz.x;
        g_accA[bA + 3] = vAx.y; g_accA[bA + 4] = vAy.y; g_accA[bA + 5] = vAz.y;
        float2 vSxx = unpack2(A.Sxx), vSyy = unpack2(A.Syy), vSzz = unpack2(A.Szz);
        float2 vSxy = unpack2(A.Sxy), vSxz = unpack2(A.Sxz), vSyz = unpack2(A.Syz);
        int bS = base * 6;
        g_accS[bS + 0] = vSxx.x; g_accS[bS + 1] = vSyy.x; g_accS[bS + 2] = vSzz.x;
        g_accS[bS + 3] = vSxy.x; g_accS[bS + 4] = vSxz.x; g_accS[bS + 5] = vSyz.x;
        g_accS[bS + 6] = vSxx.y; g_accS[bS + 7] = vSyy.y; g_accS[bS + 8] = vSzz.y;
        g_accS[bS + 9] = vSxy.y; g_accS[bS + 10] = vSxz.y; g_accS[bS + 11] = vSyz.y;
    }
}

// ------------------------------------------------------------------
// Post: tn -> LN -> MLP -> n0 -> diagonal output (merged)
// ------------------------------------------------------------------
__device__ __forceinline__ float sq(float x) { return x * x; }
__device__ __forceinline__ float silu(float x) { return x / (1.0f + expf(-x)); }

__global__ void k_post(const float* __restrict__ lng, const float* __restrict__ lnb,
                       const float* __restrict__ w1, const float* __restrict__ b1,
                       const float* __restrict__ w2, const float* __restrict__ b2,
                       const float* __restrict__ m0, const float* __restrict__ m1,
                       const float* __restrict__ m2, float* __restrict__ out, int n)
{
    extern __shared__ float sm[];
    float* w1T  = sm;               // [j(64)][o(128)]
    float* w2nT = w1T + 64 * 128;   // [j(128)][h(64)]
    float* m0T  = w2nT + 128 * 64;  // [h][k]
    float* msT  = m0T + 64 * 64;    // [h][k] of m1+m2
    float* sb1  = msT + 64 * 64;    // 128
    float* sb2  = sb1 + 128;        // 64
    float* slg  = sb2 + 64;
    float* slb  = slg + 64;
    float* wk   = slb + 64;         // NW * 320

    int tid = threadIdx.x;
    for (int i = tid; i < 64 * 128; i += blockDim.x) {
        int j = i >> 7, o = i & 127;
        w1T[i] = w1[o * 64 + j];
    }
    for (int i = tid; i < 128 * 64; i += blockDim.x) {
        int j = i >> 6, h = i & 63;
        w2nT[i] = w2[h * 3 * 128 + j];
    }
    for (int i = tid; i < 64 * 64; i += blockDim.x) {
        int h = i >> 6, k = i & 63;
        m0T[i] = m0[k * 64 + h];
        msT[i] = m1[k * 64 + h] + m2[k * 64 + h];
    }
    for (int i = tid; i < 128; i += blockDim.x) sb1[i] = b1[i];
    for (int i = tid; i < 64; i += blockDim.x) {
        sb2[i] = b2[3 * i]; slg[i] = lng[i]; slb[i] = lnb[i];
    }
    __syncthreads();

    int warp = tid >> 5, lane = tid & 31;
    float* nm  = wk + warp * 320;   // 64
    float* h1  = nm + 64;           // 128
    float* wkv = h1 + 128;          // 128
    const float2* w2n2 = (const float2*)w2nT;
    const float2* m0v  = (const float2*)m0T;
    const float2* msv  = (const float2*)msT;

    for (int atom = blockIdx.x * NW + warp; atom < n; atom += gridDim.x * NW) {
        int h0 = lane * 2;
        int base = atom * 64 + h0;
        float i0a = g_accI[base], i0b = g_accI[base + 1];
        const float* Ap = g_accA + base * 3;
        const float* Sp = g_accS + base * 6;
        float tna = sq(i0a + Sp[0]) + sq(i0a + Sp[1]) + sq(i0a + Sp[2])
                  + 2.0f * (sq(Sp[3]) + sq(Sp[4]) + sq(Sp[5]) + sq(Ap[0]) + sq(Ap[1]) + sq(Ap[2]));
        float tnb = sq(i0b + Sp[6]) + sq(i0b + Sp[7]) + sq(i0b + Sp[8])
                  + 2.0f * (sq(Sp[9]) + sq(Sp[10]) + sq(Sp[11]) + sq(Ap[3]) + sq(Ap[4]) + sq(Ap[5]));
        wkv[h0] = i0a; wkv[h0 + 1] = i0b;

        float s = tna + tnb;
        for (int o = 16; o; o >>= 1) s += __shfl_xor_sync(0xffffffffu, s, o);
        float mu = s * (1.0f / 64.0f);
        float da = tna - mu, db = tnb - mu;
        float vs = da * da + db * db;
        for (int o = 16; o; o >>= 1) vs += __shfl_xor_sync(0xffffffffu, vs, o);
        float inv = rsqrtf(vs * (1.0f / 64.0f) + 1e-5f);
        nm[h0]     = da * inv * slg[h0] + slb[h0];
        nm[h0 + 1] = db * inv * slg[h0 + 1] + slb[h0 + 1];
        __syncwarp();

        #pragma unroll
        for (int p = 0; p < 4; p++) {
            int o = lane + 32 * p;
            float acc = sb1[o];
            #pragma unroll 8
            for (int j = 0; j < 64; j++) acc = fmaf(w1T[j * 128 + o], nm[j], acc);
            h1[o] = silu(acc);
        }
        __syncwarp();

        float2 acc2 = ((const float2*)sb2)[lane];
        #pragma unroll 8
        for (int j = 0; j < 128; j++) {
            float hv = h1[j];
            float2 wv = w2n2[j * 32 + lane];
            acc2.x = fmaf(wv.x, hv, acc2.x);
            acc2.y = fmaf(wv.y, hv, acc2.y);
        }
        float n0x = silu(acc2.x), n0y = silu(acc2.y);

        float2 d1 = {0.f, 0.f};
        #pragma unroll 8
        for (int h = 0; h < 64; h++) {
            float a = wkv[h];
            float2 m = m0v[h * 32 + lane];
            d1.x = fmaf(m.x, a, d1.x);
            d1.y = fmaf(m.y, a, d1.y);
        }
        d1.x *= n0x; d1.y *= n0y;
        __syncwarp();
        wkv[h0] = d1.x; wkv[h0 + 1] = d1.y;
        __syncwarp();

        float2 tt = {0.f, 0.f};
        #pragma unroll 8
        for (int h = 0; h < 64; h++) {
            float d = wkv[h];
            float2 m = msv[h * 32 + lane];
            tt.x = fmaf(m.x, d, tt.x);
            tt.y = fmaf(m.y, d, tt.y);
        }
        float vx = d1.x + n0x * tt.x;
        float vy = d1.y + n0y * tt.y;

        float2* o = (float2*)(out + (size_t)(atom * 64 + h0) * 9);
        o[0] = make_float2(vx, 0.f);
        o[1] = make_float2(0.f, 0.f);
        o[2] = make_float2(vx, 0.f);
        o[3] = make_float2(0.f, 0.f);
        o[4] = make_float2(vx, vy);
        o[5] = make_float2(0.f, 0.f);
        o[6] = make_float2(0.f, vy);
        o[7] = make_float2(0.f, 0.f);
        o[8] = make_float2(0.f, vy);
        __syncwarp();
    }
}

// ------------------------------------------------------------------
extern "C" void kernel_launch(void* const* d_in, const int* in_sizes, int n_in,
                              void* d_out, int out_size)
{
    const int*   z    = (const int*)d_in[0];
    const int*   ei   = (const int*)d_in[1];
    const float* ew   = (const float*)d_in[2];
    const float* evn  = (const float*)d_in[3];
    const float* attr = (const float*)d_in[4];
    const float* emb  = (const float*)d_in[5];
    const float* e2w  = (const float*)d_in[6];
    const float* e2b  = (const float*)d_in[7];
    const float* d1w  = (const float*)d_in[8];
    const float* d1b  = (const float*)d_in[9];
    const float* d2w  = (const float*)d_in[10];
    const float* d2b  = (const float*)d_in[11];
    const float* d3w  = (const float*)d_in[12];
    const float* d3b  = (const float*)d_in[13];
    const float* lng  = (const float*)d_in[14];
    const float* lnb  = (const float*)d_in[15];
    const float* w1   = (const float*)d_in[16];
    const float* b1   = (const float*)d_in[17];
    const float* w2   = (const float*)d_in[18];
    const float* b2   = (const float*)d_in[19];
    const float* m0   = (const float*)d_in[20];
    const float* m1   = (const float*)d_in[21];
    const float* m2   = (const float*)d_in[22];
    float* out = (float*)d_out;

    int n    = in_sizes[0];
    int nE   = in_sizes[2];
    int maxz = in_sizes[5] / 64;
    if (maxz > 256) maxz = 256;

    size_t smemG = (size_t)(2 * 128 * 68) * sizeof(unsigned);   // 69632 B
    size_t smemP = (size_t)(64 * 128 + 128 * 64 + 2 * 64 * 64 + 128 + 3 * 64 + NW * 320) * sizeof(float);
    cudaFuncSetAttribute(k_gemm, cudaFuncAttributeMaxDynamicSharedMemorySize, (int)smemG);
    cudaFuncSetAttribute(k_post, cudaFuncAttributeMaxDynamicSharedMemorySize, (int)smemP);

    k_zero<<<(n + 255) / 256, 256>>>(n);
    k_count<<<(nE + 255) / 256, 256>>>(ei, nE);
    k_pre<<<maxz, 64>>>(emb, e2w, e2b);
    k_wprep<<<24, 256>>>(d1w, d2w, d3w);
    k_scan<<<1, 1024>>>(n);
    k_scatter<<<(nE + 255) / 256, 256>>>(ei, nE);
    k_gather<<<(nE + 255) / 256, 256>>>(ei, z, ew, evn, nE);

    k_gemm<<<(nE + 127) / 128, 256, smemG>>>(attr, nE);
    k_reduce<<<152, 512>>>(z, d1b, d2b, d3b, n);
    k_post<<<304, NW * 32, smemP>>>(lng, lnb, w1, b1, w2, b2, m0, m1, m2, out, n);
}